// round 1
// baseline (speedup 1.0000x reference)
#include <cuda_runtime.h>
#include <math.h>

#define H 1024
#define L 4096
#define V 29

// ---------------- scratch (device globals; no allocation allowed) ----------
__device__ float g_scores[L];
__device__ float g_attn_applied[H];
__device__ float g_x[H];
__device__ float g_gates[4 * H];

// ---------------- helpers ---------------------------------------------------
__device__ __forceinline__ float warp_sum(float v) {
#pragma unroll
    for (int o = 16; o; o >>= 1) v += __shfl_xor_sync(0xffffffffu, v, o);
    return v;
}
__device__ __forceinline__ float warp_max(float v) {
#pragma unroll
    for (int o = 16; o; o >>= 1) v = fmaxf(v, __shfl_xor_sync(0xffffffffu, v, o));
    return v;
}
__device__ __forceinline__ float sigmoidf_(float x) { return 1.0f / (1.0f + expf(-x)); }

// ---------------- K0: zero the attn_applied accumulator --------------------
__global__ void k_prep() {
    int i = blockIdx.x * blockDim.x + threadIdx.x;
    if (i < H) g_attn_applied[i] = 0.0f;
}

// ---------------- K1: scores = attn_W @ [emb[tok]; h0] + attn_b ------------
// One warp per output row. cat1 cached in shared memory per block.
__global__ void k_attn_scores(const int* __restrict__ tok,
                              const float* __restrict__ emb,
                              const float* __restrict__ h0,
                              const float* __restrict__ attn_W,
                              const float* __restrict__ attn_b) {
    __shared__ float s[2 * H];
    int t = threadIdx.x;
    const float* erow = emb + (size_t)tok[0] * H;
    for (int i = t; i < H; i += blockDim.x) {
        s[i] = erow[i];
        s[H + i] = h0[i];
    }
    __syncthreads();

    int warp = t >> 5, lane = t & 31;
    int row = blockIdx.x * 8 + warp;   // gridDim.x = L/8 = 512
    const float4* w = (const float4*)(attn_W + (size_t)row * (2 * H));
    const float4* c = (const float4*)s;
    float acc = 0.0f;
#pragma unroll 4
    for (int j = lane; j < (2 * H) / 4; j += 32) {
        float4 a = w[j], b = c[j];
        acc += a.x * b.x + a.y * b.y + a.z * b.z + a.w * b.w;
    }
    acc = warp_sum(acc);
    if (lane == 0) g_scores[row] = acc + attn_b[row];
}

// ---------------- K2: softmax over L, write attn_weights to d_out ----------
// Single block, 1024 threads, 4 elements each.
__global__ void k_softmax(float* __restrict__ attn_out) {
    __shared__ float red[32];
    __shared__ float bcast;
    int t = threadIdx.x;
    int warp = t >> 5, lane = t & 31;

    float v[4];
    float m = -1e30f;
#pragma unroll
    for (int k = 0; k < 4; k++) {
        v[k] = g_scores[t + k * 1024];
        m = fmaxf(m, v[k]);
    }
    m = warp_max(m);
    if (lane == 0) red[warp] = m;
    __syncthreads();
    if (warp == 0) {
        float x = red[lane];
        x = warp_max(x);
        if (lane == 0) bcast = x;
    }
    __syncthreads();
    float M = bcast;

    float sum = 0.0f;
#pragma unroll
    for (int k = 0; k < 4; k++) {
        v[k] = expf(v[k] - M);
        sum += v[k];
    }
    sum = warp_sum(sum);
    if (lane == 0) red[warp] = sum;
    __syncthreads();
    if (warp == 0) {
        float x = red[lane];
        x = warp_sum(x);
        if (lane == 0) bcast = x;
    }
    __syncthreads();
    float inv = 1.0f / bcast;
#pragma unroll
    for (int k = 0; k < 4; k++) attn_out[t + k * 1024] = v[k] * inv;
}

// ---------------- K3: attn_applied = attn_weights @ encoder_outputs --------
// grid = (H/256, 32); each block accumulates a 128-row slice of L, atomicAdd.
__global__ void k_attn_apply(const float* __restrict__ wts,
                             const float* __restrict__ enc) {
    int h = blockIdx.x * blockDim.x + threadIdx.x;
    int lb = blockIdx.y * (L / 32);
    float acc = 0.0f;
#pragma unroll 4
    for (int l = lb; l < lb + (L / 32); l++) {
        acc += wts[l] * enc[(size_t)l * H + h];
    }
    atomicAdd(&g_attn_applied[h], acc);
}

// ---------------- K4: x = relu(comb_W @ [emb[tok]; attn_applied] + comb_b) -
__global__ void k_combine(const int* __restrict__ tok,
                          const float* __restrict__ emb,
                          const float* __restrict__ comb_W,
                          const float* __restrict__ comb_b) {
    __shared__ float s[2 * H];
    int t = threadIdx.x;
    const float* erow = emb + (size_t)tok[0] * H;
    for (int i = t; i < H; i += blockDim.x) {
        s[i] = erow[i];
        s[H + i] = g_attn_applied[i];
    }
    __syncthreads();

    int warp = t >> 5, lane = t & 31;
    int row = blockIdx.x * 8 + warp;   // gridDim.x = H/8 = 128
    const float4* w = (const float4*)(comb_W + (size_t)row * (2 * H));
    const float4* c = (const float4*)s;
    float acc = 0.0f;
#pragma unroll 4
    for (int j = lane; j < (2 * H) / 4; j += 32) {
        float4 a = w[j], b = c[j];
        acc += a.x * b.x + a.y * b.y + a.z * b.z + a.w * b.w;
    }
    acc = warp_sum(acc);
    if (lane == 0) g_x[row] = fmaxf(acc + comb_b[row], 0.0f);
}

// ---------------- K5: gates = W_ih @ x + W_hh @ h0 + b_ih + b_hh -----------
__global__ void k_gates(const float* __restrict__ h0,
                        const float* __restrict__ W_ih,
                        const float* __restrict__ W_hh,
                        const float* __restrict__ b_ih,
                        const float* __restrict__ b_hh) {
    __shared__ float s[2 * H];   // [x ; h0]
    int t = threadIdx.x;
    for (int i = t; i < H; i += blockDim.x) {
        s[i] = g_x[i];
        s[H + i] = h0[i];
    }
    __syncthreads();

    int warp = t >> 5, lane = t & 31;
    int row = blockIdx.x * 8 + warp;   // gridDim.x = 4H/8 = 512
    const float4* wi = (const float4*)(W_ih + (size_t)row * H);
    const float4* wh = (const float4*)(W_hh + (size_t)row * H);
    const float4* sx = (const float4*)s;
    const float4* sh = (const float4*)(s + H);
    float acc = 0.0f;
#pragma unroll
    for (int j = lane; j < H / 4; j += 32) {
        float4 a = wi[j], b = sx[j];
        acc += a.x * b.x + a.y * b.y + a.z * b.z + a.w * b.w;
        float4 a2 = wh[j], b2 = sh[j];
        acc += a2.x * b2.x + a2.y * b2.y + a2.z * b2.z + a2.w * b2.w;
    }
    acc = warp_sum(acc);
    if (lane == 0) g_gates[row] = acc + b_ih[row] + b_hh[row];
}

// ---------------- K6: LSTM pointwise; write h_new, c_new into d_out --------
__global__ void k_lstm(const float* __restrict__ c0, float* __restrict__ out) {
    int i = blockIdx.x * blockDim.x + threadIdx.x;
    if (i >= H) return;
    float ig = g_gates[i];
    float fg = g_gates[H + i];
    float gg = g_gates[2 * H + i];
    float og = g_gates[3 * H + i];
    float c = sigmoidf_(fg) * c0[i] + sigmoidf_(ig) * tanhf(gg);
    float h = sigmoidf_(og) * tanhf(c);
    out[V + i] = h;
    out[V + H + i] = c;
}

// ---------------- K7: log_probs = log_softmax(out_W @ h_new + out_b) -------
// Single block, 1024 threads; warp r (< V) computes row r.
__global__ void k_out(const float* __restrict__ out_W,
                      const float* __restrict__ out_b,
                      float* __restrict__ out) {
    __shared__ float z[32];
    const float* h = out + V;   // h_new written by k_lstm
    int t = threadIdx.x;
    int warp = t >> 5, lane = t & 31;
    if (warp < V) {
        const float* wr = out_W + (size_t)warp * H;
        float acc = 0.0f;
#pragma unroll
        for (int k = lane; k < H; k += 32) acc += wr[k] * h[k];
        acc = warp_sum(acc);
        if (lane == 0) z[warp] = acc + out_b[warp];
    }
    __syncthreads();
    if (t == 0) {
        float m = -1e30f;
        for (int r = 0; r < V; r++) m = fmaxf(m, z[r]);
        float s = 0.0f;
        for (int r = 0; r < V; r++) s += expf(z[r] - m);
        float ls = m + logf(s);
        for (int r = 0; r < V; r++) out[r] = z[r] - ls;
    }
}

// ---------------- launch ----------------------------------------------------
extern "C" void kernel_launch(void* const* d_in, const int* in_sizes, int n_in,
                              void* d_out, int out_size) {
    const int*   tok    = (const int*)  d_in[0];
    const float* h0     = (const float*)d_in[1];
    const float* c0     = (const float*)d_in[2];
    const float* enc    = (const float*)d_in[3];
    const float* emb    = (const float*)d_in[4];
    const float* attn_W = (const float*)d_in[5];
    const float* attn_b = (const float*)d_in[6];
    const float* comb_W = (const float*)d_in[7];
    const float* comb_b = (const float*)d_in[8];
    const float* W_ih   = (const float*)d_in[9];
    const float* W_hh   = (const float*)d_in[10];
    const float* b_ih   = (const float*)d_in[11];
    const float* b_hh   = (const float*)d_in[12];
    const float* out_W  = (const float*)d_in[13];
    const float* out_b  = (const float*)d_in[14];
    float* out = (float*)d_out;

    float* attn_weights_out = out + V + 2 * H;   // d_out layout: [lp | h | c | attn_w]

    k_prep<<<4, 256>>>();
    k_attn_scores<<<L / 8, 256>>>(tok, emb, h0, attn_W, attn_b);
    k_softmax<<<1, 1024>>>(attn_weights_out);
    {
        dim3 g(H / 256, 32);
        k_attn_apply<<<g, 256>>>(attn_weights_out, enc);
    }
    k_combine<<<H / 8, 256>>>(tok, emb, comb_W, comb_b);
    k_gates<<<(4 * H) / 8, 256>>>(h0, W_ih, W_hh, b_ih, b_hh);
    k_lstm<<<4, 256>>>(c0, out);
    k_out<<<1, 1024>>>(out_W, out_b, out);
}

// round 2
// speedup vs baseline: 1.1533x; 1.1533x over previous
#include <cuda_runtime.h>
#include <math.h>

#define H 1024
#define L 4096
#define V 29

#define NSLICE 256
#define RPS (L / NSLICE)   // 16 encoder rows per block

// ---------------- scratch (device globals; no allocation allowed) ----------
__device__ float g_scores[L];
__device__ float g_attn_applied[H];
__device__ float g_x[H];
__device__ float g_gates[4 * H];

// ---------------- helpers ---------------------------------------------------
__device__ __forceinline__ float warp_sum(float v) {
#pragma unroll
    for (int o = 16; o; o >>= 1) v += __shfl_xor_sync(0xffffffffu, v, o);
    return v;
}
__device__ __forceinline__ float warp_max(float v) {
#pragma unroll
    for (int o = 16; o; o >>= 1) v = fmaxf(v, __shfl_xor_sync(0xffffffffu, v, o));
    return v;
}
__device__ __forceinline__ float sigmoidf_(float x) { return 1.0f / (1.0f + expf(-x)); }

// ---------------- K1: scores = attn_W @ [emb[tok]; h0] + attn_b ------------
// One warp per output row. Block 0 also zeroes the attn_applied accumulator.
__global__ void k_attn_scores(const int* __restrict__ tok,
                              const float* __restrict__ emb,
                              const float* __restrict__ h0,
                              const float* __restrict__ attn_W,
                              const float* __restrict__ attn_b) {
    __shared__ float s[2 * H];
    int t = threadIdx.x;
    if (blockIdx.x == 0) {
#pragma unroll
        for (int i = t; i < H; i += 256) g_attn_applied[i] = 0.0f;
    }
    const float* erow = emb + (size_t)tok[0] * H;
    for (int i = t; i < H; i += blockDim.x) {
        s[i] = erow[i];
        s[H + i] = h0[i];
    }
    __syncthreads();

    int warp = t >> 5, lane = t & 31;
    int row = blockIdx.x * 8 + warp;   // gridDim.x = L/8 = 512
    const float4* w = (const float4*)(attn_W + (size_t)row * (2 * H));
    const float4* c = (const float4*)s;
    float acc = 0.0f;
#pragma unroll 8
    for (int j = lane; j < (2 * H) / 4; j += 32) {
        float4 a = w[j], b = c[j];
        acc += a.x * b.x + a.y * b.y + a.z * b.z + a.w * b.w;
    }
    acc = warp_sum(acc);
    if (lane == 0) g_scores[row] = acc + attn_b[row];
}

// ---------------- K2: fused softmax + attn_applied = w @ enc ---------------
// grid = NSLICE blocks of 256 threads. Each block:
//   (a) block-reduces max & sum of all L scores (redundant, from L2, cheap)
//   (b) computes weights for its 16 rows, writes them to d_out
//   (c) accumulates its 16-row slice of the weighted sum, atomicAdd to global
__global__ void k_attn_apply(const float* __restrict__ enc,
                             float* __restrict__ attn_out) {
    __shared__ float red[32];
    __shared__ float bcast;
    __shared__ float wts[RPS];
    int t = threadIdx.x;
    int warp = t >> 5, lane = t & 31;

    float sc[16];
    float m = -1e30f;
#pragma unroll
    for (int k = 0; k < 16; k++) {
        sc[k] = g_scores[t + k * 256];
        m = fmaxf(m, sc[k]);
    }
    m = warp_max(m);
    if (lane == 0) red[warp] = m;
    __syncthreads();
    if (warp == 0) {
        float x = red[lane & 7];   // 8 warps
        x = warp_max(x);
        if (lane == 0) bcast = x;
    }
    __syncthreads();
    float M = bcast;

    float sum = 0.0f;
#pragma unroll
    for (int k = 0; k < 16; k++) sum += expf(sc[k] - M);
    sum = warp_sum(sum);
    __syncthreads();
    if (lane == 0) red[warp] = sum;
    __syncthreads();
    if (warp == 0) {
        float x = (lane < 8) ? red[lane] : 0.0f;
        x = warp_sum(x);
        if (lane == 0) bcast = x;
    }
    __syncthreads();
    float invS = 1.0f / bcast;

    int lb = blockIdx.x * RPS;
    if (t < RPS) {
        float w = expf(g_scores[lb + t] - M) * invS;
        wts[t] = w;
        attn_out[lb + t] = w;
    }
    __syncthreads();

    // weighted sum: thread t owns float4 column slot t (256*4 = 1024 = H)
    const float4* e = (const float4*)(enc + (size_t)lb * H);
    float4 acc = make_float4(0.f, 0.f, 0.f, 0.f);
#pragma unroll
    for (int r = 0; r < RPS; r++) {
        float4 v = e[(size_t)r * (H / 4) + t];
        float w = wts[r];
        acc.x += w * v.x; acc.y += w * v.y; acc.z += w * v.z; acc.w += w * v.w;
    }
    float* dst = g_attn_applied + 4 * t;
    atomicAdd(dst + 0, acc.x);
    atomicAdd(dst + 1, acc.y);
    atomicAdd(dst + 2, acc.z);
    atomicAdd(dst + 3, acc.w);
}

// ---------------- K3: x = relu(comb_W @ [emb[tok]; attn_applied] + comb_b) -
// 256 blocks x 128 threads, one warp per output row.
__global__ void k_combine(const int* __restrict__ tok,
                          const float* __restrict__ emb,
                          const float* __restrict__ comb_W,
                          const float* __restrict__ comb_b) {
    __shared__ float s[2 * H];
    int t = threadIdx.x;
    const float* erow = emb + (size_t)tok[0] * H;
    for (int i = t; i < H; i += blockDim.x) {
        s[i] = erow[i];
        s[H + i] = g_attn_applied[i];
    }
    __syncthreads();

    int warp = t >> 5, lane = t & 31;
    int row = blockIdx.x * 4 + warp;   // gridDim.x = H/4 = 256
    const float4* w = (const float4*)(comb_W + (size_t)row * (2 * H));
    const float4* c = (const float4*)s;
    float acc = 0.0f;
#pragma unroll 8
    for (int j = lane; j < (2 * H) / 4; j += 32) {
        float4 a = w[j], b = c[j];
        acc += a.x * b.x + a.y * b.y + a.z * b.z + a.w * b.w;
    }
    acc = warp_sum(acc);
    if (lane == 0) g_x[row] = fmaxf(acc + comb_b[row], 0.0f);
}

// ---------------- K4: gates = W_ih @ x + W_hh @ h0 + b_ih + b_hh -----------
__global__ void k_gates(const float* __restrict__ h0,
                        const float* __restrict__ W_ih,
                        const float* __restrict__ W_hh,
                        const float* __restrict__ b_ih,
                        const float* __restrict__ b_hh) {
    __shared__ float s[2 * H];   // [x ; h0]
    int t = threadIdx.x;
    for (int i = t; i < H; i += blockDim.x) {
        s[i] = g_x[i];
        s[H + i] = h0[i];
    }
    __syncthreads();

    int warp = t >> 5, lane = t & 31;
    int row = blockIdx.x * 8 + warp;   // gridDim.x = 4H/8 = 512
    const float4* wi = (const float4*)(W_ih + (size_t)row * H);
    const float4* wh = (const float4*)(W_hh + (size_t)row * H);
    const float4* sx = (const float4*)s;
    const float4* sh = (const float4*)(s + H);
    float acc = 0.0f;
#pragma unroll
    for (int j = lane; j < H / 4; j += 32) {
        float4 a = wi[j], b = sx[j];
        acc += a.x * b.x + a.y * b.y + a.z * b.z + a.w * b.w;
        float4 a2 = wh[j], b2 = sh[j];
        acc += a2.x * b2.x + a2.y * b2.y + a2.z * b2.z + a2.w * b2.w;
    }
    acc = warp_sum(acc);
    if (lane == 0) g_gates[row] = acc + b_ih[row] + b_hh[row];
}

// ---------------- K5: fused LSTM pointwise + out proj + log_softmax --------
// Single block, 1024 threads. Phase 1: LSTM pointwise (writes h,c to d_out
// and shared). Phase 2: warps 0..28 compute out_W rows. Phase 3: log_softmax.
__global__ void k_out(const float* __restrict__ c0,
                      const float* __restrict__ out_W,
                      const float* __restrict__ out_b,
                      float* __restrict__ out) {
    __shared__ float sh_h[H];
    __shared__ float z[32];
    int t = threadIdx.x;
    int warp = t >> 5, lane = t & 31;

    // LSTM pointwise
    {
        float ig = g_gates[t];
        float fg = g_gates[H + t];
        float gg = g_gates[2 * H + t];
        float og = g_gates[3 * H + t];
        float c = sigmoidf_(fg) * c0[t] + sigmoidf_(ig) * tanhf(gg);
        float h = sigmoidf_(og) * tanhf(c);
        out[V + t] = h;
        out[V + H + t] = c;
        sh_h[t] = h;
    }
    __syncthreads();

    // output projection (warp per vocab row)
    if (warp < V) {
        const float4* wr = (const float4*)(out_W + (size_t)warp * H);
        const float4* hv = (const float4*)sh_h;
        float acc = 0.0f;
#pragma unroll
        for (int k = lane; k < H / 4; k += 32) {
            float4 a = wr[k], b = hv[k];
            acc += a.x * b.x + a.y * b.y + a.z * b.z + a.w * b.w;
        }
        acc = warp_sum(acc);
        if (lane == 0) z[warp] = acc + out_b[warp];
    }
    __syncthreads();

    // log_softmax over V=29 (single thread; tiny)
    if (t == 0) {
        float m = -1e30f;
        for (int r = 0; r < V; r++) m = fmaxf(m, z[r]);
        float s = 0.0f;
        for (int r = 0; r < V; r++) s += expf(z[r] - m);
        float ls = m + logf(s);
        for (int r = 0; r < V; r++) out[r] = z[r] - ls;
    }
}

// ---------------- launch ----------------------------------------------------
extern "C" void kernel_launch(void* const* d_in, const int* in_sizes, int n_in,
                              void* d_out, int out_size) {
    const int*   tok    = (const int*)  d_in[0];
    const float* h0     = (const float*)d_in[1];
    const float* c0     = (const float*)d_in[2];
    const float* enc    = (const float*)d_in[3];
    const float* emb    = (const float*)d_in[4];
    const float* attn_W = (const float*)d_in[5];
    const float* attn_b = (const float*)d_in[6];
    const float* comb_W = (const float*)d_in[7];
    const float* comb_b = (const float*)d_in[8];
    const float* W_ih   = (const float*)d_in[9];
    const float* W_hh   = (const float*)d_in[10];
    const float* b_ih   = (const float*)d_in[11];
    const float* b_hh   = (const float*)d_in[12];
    const float* out_W  = (const float*)d_in[13];
    const float* out_b  = (const float*)d_in[14];
    float* out = (float*)d_out;

    float* attn_weights_out = out + V + 2 * H;   // layout: [lp | h | c | attn_w]

    k_attn_scores<<<L / 8, 256>>>(tok, emb, h0, attn_W, attn_b);
    k_attn_apply<<<NSLICE, 256>>>(enc, attn_weights_out);
    k_combine<<<H / 4, 128>>>(tok, emb, comb_W, comb_b);
    k_gates<<<(4 * H) / 8, 256>>>(h0, W_ih, W_hh, b_ih, b_hh);
    k_out<<<1, 1024>>>(c0, out_W, out_b, out);
}

// round 3
// speedup vs baseline: 1.5828x; 1.3725x over previous
#include <cuda_runtime.h>
#include <math.h>

#define H 1024
#define L 4096
#define V 29
#define NB 128           // blocks (<= SM count, 1 block/SM -> co-resident)
#define NT 1024          // threads per block
#define WPB 32           // warps per block

// ---------------- scratch (device globals) ----------------------------------
__device__ float g_scores[L];
__device__ float g_hh[4 * H];          // W_hh @ h0 partial gates
__device__ float g_attn_applied[H];
__device__ float g_x[H];
__device__ float g_gates[4 * H];
__device__ unsigned g_cnt = 0;
__device__ volatile unsigned g_flag = 0;

// ---------------- helpers ----------------------------------------------------
__device__ __forceinline__ float warp_sum(float v) {
#pragma unroll
    for (int o = 16; o; o >>= 1) v += __shfl_xor_sync(0xffffffffu, v, o);
    return v;
}
__device__ __forceinline__ float warp_max(float v) {
#pragma unroll
    for (int o = 16; o; o >>= 1) v = fmaxf(v, __shfl_xor_sync(0xffffffffu, v, o));
    return v;
}
__device__ __forceinline__ float sigmoidf_(float x) { return 1.0f / (1.0f + expf(-x)); }

// sense-reversing grid barrier. Requires all NB blocks co-resident.
// Counter self-resets; flag must return to 0 at kernel end (use EVEN # of barriers).
__device__ __forceinline__ void grid_barrier(unsigned sense) {
    __syncthreads();
    if (threadIdx.x == 0) {
        __threadfence();
        unsigned old = atomicAdd(&g_cnt, 1u);
        if (old == NB - 1) {
            g_cnt = 0;
            __threadfence();
            g_flag = sense;
        } else {
            while (g_flag != sense) { __nanosleep(64); }
        }
        __threadfence();
    }
    __syncthreads();
}

__device__ __forceinline__ float dot4(float4 a, float4 b) {
    return a.x * b.x + a.y * b.y + a.z * b.z + a.w * b.w;
}

// ---------------- the whole decoder step in one kernel -----------------------
__global__ void __launch_bounds__(NT, 1)
k_decoder(const int* __restrict__ tok,
          const float* __restrict__ h0,
          const float* __restrict__ c0,
          const float* __restrict__ enc,
          const float* __restrict__ emb,
          const float* __restrict__ attn_W,
          const float* __restrict__ attn_b,
          const float* __restrict__ comb_W,
          const float* __restrict__ comb_b,
          const float* __restrict__ W_ih,
          const float* __restrict__ W_hh,
          const float* __restrict__ b_ih,
          const float* __restrict__ b_hh,
          const float* __restrict__ out_W,
          const float* __restrict__ out_b,
          float* __restrict__ out) {
    __shared__ float s[2 * H];
    __shared__ float red[32];
    __shared__ float bcast;
    __shared__ float wts[32];
    __shared__ float z[32];

    const int t = threadIdx.x;          // 0..1023
    const int warp = t >> 5, lane = t & 31;
    float* attn_out = out + V + 2 * H;  // d_out layout: [lp | h | c | attn_w]

    // ============ Phase A: attn scores + W_hh@h0 (independent, fused) =======
    {
        const float* erow = emb + (size_t)tok[0] * H;
        s[t] = erow[t];
        s[H + t] = h0[t];
        if (blockIdx.x == 0) g_attn_applied[t] = 0.0f;
        __syncthreads();

        int gw = blockIdx.x * WPB + warp;   // 0..4095

        // scores row gw: dot over 2H
        {
            const float4* w = (const float4*)(attn_W + (size_t)gw * (2 * H));
            const float4* c = (const float4*)s;
            float acc = 0.0f;
#pragma unroll 4
            for (int j = lane; j < (2 * H) / 4; j += 32) acc += dot4(w[j], c[j]);
            acc = warp_sum(acc);
            if (lane == 0) g_scores[gw] = acc + attn_b[gw];
        }
        // hh row gw: dot over H
        {
            const float4* w = (const float4*)(W_hh + (size_t)gw * H);
            const float4* c = (const float4*)(s + H);
            float acc = 0.0f;
#pragma unroll 4
            for (int j = lane; j < H / 4; j += 32) acc += dot4(w[j], c[j]);
            acc = warp_sum(acc);
            if (lane == 0) g_hh[gw] = acc;
        }
    }
    grid_barrier(1);

    // ============ Phase B: softmax (redundant per-block) + weighted enc sum ==
    {
        float sc[4];
        float m = -1e30f;
#pragma unroll
        for (int k = 0; k < 4; k++) {
            sc[k] = g_scores[t + k * 1024];
            m = fmaxf(m, sc[k]);
        }
        m = warp_max(m);
        if (lane == 0) red[warp] = m;
        __syncthreads();
        if (warp == 0) {
            float x = red[lane];
            x = warp_max(x);
            if (lane == 0) bcast = x;
        }
        __syncthreads();
        const float M = bcast;

        float sum = 0.0f;
#pragma unroll
        for (int k = 0; k < 4; k++) sum += expf(sc[k] - M);
        sum = warp_sum(sum);
        __syncthreads();
        if (lane == 0) red[warp] = sum;
        __syncthreads();
        if (warp == 0) {
            float x = red[lane];
            x = warp_sum(x);
            if (lane == 0) bcast = x;
        }
        __syncthreads();
        const float invS = 1.0f / bcast;

        const int lb = blockIdx.x * 32;    // this block's 32 encoder rows
        if (t < 32) {
            float w = expf(g_scores[lb + t] - M) * invS;
            wts[t] = w;
            attn_out[lb + t] = w;
        }
        __syncthreads();

        // thread t owns column t (1024 threads = H columns), fully coalesced
        float acc = 0.0f;
        const float* e = enc + (size_t)lb * H + t;
#pragma unroll 8
        for (int r = 0; r < 32; r++) acc += wts[r] * e[(size_t)r * H];
        atomicAdd(&g_attn_applied[t], acc);
    }
    grid_barrier(0);

    // ============ Phase C: x = relu(comb_W @ [emb; attn_applied] + b) =======
    {
        s[H + t] = g_attn_applied[t];      // emb still resident in s[0..H)
        __syncthreads();

        int row = blockIdx.x * 8 + (warp >> 2);   // 8 rows/block, 4 warps/row
        int part = warp & 3;
        const float4* w = (const float4*)(comb_W + (size_t)row * (2 * H));
        const float4* c = (const float4*)s;
        float acc = 0.0f;
        int j0 = part * 128 + lane;
#pragma unroll
        for (int j = j0; j < part * 128 + 128; j += 32) acc += dot4(w[j], c[j]);
        acc = warp_sum(acc);
        if (lane == 0) red[warp] = acc;
        __syncthreads();
        if (warp == 0 && lane < 8) {
            int r2 = blockIdx.x * 8 + lane;
            float v = red[lane * 4] + red[lane * 4 + 1] +
                      red[lane * 4 + 2] + red[lane * 4 + 3];
            g_x[r2] = fmaxf(v + comb_b[r2], 0.0f);
        }
    }
    grid_barrier(1);

    // ============ Phase D: gates = W_ih@x + hh + b_ih + b_hh ================
    {
        s[t] = g_x[t];
        s[H + t] = h0[t];
        __syncthreads();

        int row = blockIdx.x * 32 + warp;  // 4096 rows over 128 blocks
        const float4* w = (const float4*)(W_ih + (size_t)row * H);
        const float4* c = (const float4*)s;
        float acc = 0.0f;
#pragma unroll 4
        for (int j = lane; j < H / 4; j += 32) acc += dot4(w[j], c[j]);
        acc = warp_sum(acc);
        if (lane == 0)
            g_gates[row] = acc + g_hh[row] + b_ih[row] + b_hh[row];
    }
    grid_barrier(0);

    // ============ Phase E: LSTM pointwise + out proj + log_softmax =========
    if (blockIdx.x == 0) {
        float ig = g_gates[t];
        float fg = g_gates[H + t];
        float gg = g_gates[2 * H + t];
        float og = g_gates[3 * H + t];
        float c = sigmoidf_(fg) * c0[t] + sigmoidf_(ig) * tanhf(gg);
        float h = sigmoidf_(og) * tanhf(c);
        out[V + t] = h;
        out[V + H + t] = c;
        s[t] = h;
        __syncthreads();

        if (warp < V) {
            const float4* wr = (const float4*)(out_W + (size_t)warp * H);
            const float4* hv = (const float4*)s;
            float acc = 0.0f;
#pragma unroll
            for (int k = lane; k < H / 4; k += 32) acc += dot4(wr[k], hv[k]);
            acc = warp_sum(acc);
            if (lane == 0) z[warp] = acc + out_b[warp];
        }
        __syncthreads();

        if (t == 0) {
            float m = -1e30f;
            for (int r = 0; r < V; r++) m = fmaxf(m, z[r]);
            float ssum = 0.0f;
            for (int r = 0; r < V; r++) ssum += expf(z[r] - m);
            float ls = m + logf(ssum);
            for (int r = 0; r < V; r++) out[r] = z[r] - ls;
        }
    }
}

// ---------------- launch ------------------------------------------------------
extern "C" void kernel_launch(void* const* d_in, const int* in_sizes, int n_in,
                              void* d_out, int out_size) {
    const int*   tok    = (const int*)  d_in[0];
    const float* h0     = (const float*)d_in[1];
    const float* c0     = (const float*)d_in[2];
    const float* enc    = (const float*)d_in[3];
    const float* emb    = (const float*)d_in[4];
    const float* attn_W = (const float*)d_in[5];
    const float* attn_b = (const float*)d_in[6];
    const float* comb_W = (const float*)d_in[7];
    const float* comb_b = (const float*)d_in[8];
    const float* W_ih   = (const float*)d_in[9];
    const float* W_hh   = (const float*)d_in[10];
    const float* b_ih   = (const float*)d_in[11];
    const float* b_hh   = (const float*)d_in[12];
    const float* out_W  = (const float*)d_in[13];
    const float* out_b  = (const float*)d_in[14];
    float* out = (float*)d_out;

    k_decoder<<<NB, NT>>>(tok, h0, c0, enc, emb, attn_W, attn_b,
                          comb_W, comb_b, W_ih, W_hh, b_ih, b_hh,
                          out_W, out_b, out);
}